// round 3
// baseline (speedup 1.0000x reference)
#include <cuda_runtime.h>
#include <math.h>

#define CDIM 128
#define HDIM 8
#define DDIM 16
#define NMAX 100000
#define EMAX 800000

// ---------------- device scratch (static, no allocations) ----------------
__device__ float g_qA[NMAX * CDIM];
__device__ float g_qB[NMAX * CDIM];
__device__ float g_kr[3][NMAX * CDIM];
__device__ float g_vr[3][NMAX * CDIM];
__device__ float g_sum[3][NMAX * HDIM];      // per-relation segment sums of exp
__device__ float g_aggR[3][NMAX * CDIM];     // per-relation UNNORMALIZED sum(ev * vr)
__device__ float g_Wkr[3][CDIM * CDIM];
__device__ float g_Wvr[3][CDIM * CDIM];
__device__ float g_bkr[3][CDIM];
__device__ float g_bvr[3][CDIM];

// ---------------- fold a_rel/m_rel into projection weights ----------------
// kr = (x Wk + bk) . A  ==  x (Wk.A) + (bk.A): fold per-head 16x16 transform.
__global__ void prep_weights_k(const float* __restrict__ Wk, const float* __restrict__ bk,
                               const float* __restrict__ Wv, const float* __restrict__ bv,
                               const float* __restrict__ a_rel, const float* __restrict__ m_rel) {
    int r = blockIdx.y;       // relation 0..2
    int cin = blockIdx.x;     // 0..127
    int j = threadIdx.x;      // 0..127 output col
    int s = (r == 1) ? 1 : 0; // src node type
    int h = j >> 4, e = j & 15;
    const float* wkrow = Wk + s * CDIM * CDIM + cin * CDIM + h * DDIM;
    const float* wvrow = Wv + s * CDIM * CDIM + cin * CDIM + h * DDIM;
    const float* ar = a_rel + ((r * HDIM + h) * DDIM) * DDIM + e; // stride DDIM per d
    const float* mr = m_rel + ((r * HDIM + h) * DDIM) * DDIM + e;
    float sk = 0.f, sv = 0.f;
#pragma unroll
    for (int d = 0; d < DDIM; d++) {
        sk += wkrow[d] * ar[d * DDIM];
        sv += wvrow[d] * mr[d * DDIM];
    }
    g_Wkr[r][cin * CDIM + j] = sk;
    g_Wvr[r][cin * CDIM + j] = sv;
    if (cin == 0) {
        const float* bkrow = bk + s * CDIM + h * DDIM;
        const float* bvrow = bv + s * CDIM + h * DDIM;
        float tk = 0.f, tv = 0.f;
#pragma unroll
        for (int d = 0; d < DDIM; d++) {
            tk += bkrow[d] * ar[d * DDIM];
            tv += bvrow[d] * mr[d * DDIM];
        }
        g_bkr[r][j] = tk;
        g_bvr[r][j] = tv;
    }
}

// ---------------- SGEMM: C[M,128] = f(A-source)[M,128] @ W[128,128] + b ----------
// MODE 0: A = X                       (plain projection)
// MODE 1: A = gelu(agg0/s0)           (epilogue, 1 relation)  + sigmoid-skip blend
// MODE 2: A = gelu(agg1/s1 + agg2/s2) (epilogue, 2 relations) + sigmoid-skip blend
// BM=128, BN=128, BK=16, 256 threads, 8x8 microtile in split-4+64 layout
// (conflict-free LDS.128 phases on both A and B fragments).
__device__ __forceinline__ float gelu_exact(float x) {
    return 0.5f * x * (1.0f + erff(x * 0.70710678118654752f));
}

template <int MODE>
__global__ __launch_bounds__(256) void sgemm128_k(
    const float* __restrict__ X, const float* __restrict__ X2,
    const float* __restrict__ s0p, const float* __restrict__ s1p,
    const float* __restrict__ W, const float* __restrict__ bias,
    const float* __restrict__ skipv, int tsel, const float* __restrict__ Xres,
    float* __restrict__ Cout, int M) {
    __shared__ float As[16][CDIM];
    __shared__ float Bs[16][CDIM];
    int t = threadIdx.x;
    int m0 = blockIdx.x * 128;
    int trow = t >> 4;  // 0..15
    int tcol = t & 15;  // 0..15
    float acc[8][8];
#pragma unroll
    for (int i = 0; i < 8; i++)
#pragma unroll
        for (int j = 0; j < 8; j++) acc[i][j] = 0.f;

    int rows = M - m0;
    if (rows > 128) rows = 128;

    // A-tile load: thread -> row ar (0..127), cols [k0+ac, k0+ac+8)
    int ar = t >> 1;
    int ac = (t & 1) * 8;
    // B-tile load: thread -> row br (0..15), cols [bc, bc+8)
    int br = t >> 4;
    int bc = (t & 15) * 8;

    for (int k0 = 0; k0 < CDIM; k0 += 16) {
        float4 av0 = make_float4(0.f, 0.f, 0.f, 0.f);
        float4 av1 = make_float4(0.f, 0.f, 0.f, 0.f);
        if (ar < rows) {
            const float* xp = X + (size_t)(m0 + ar) * CDIM + k0 + ac;
            av0 = *(const float4*)(xp);
            av1 = *(const float4*)(xp + 4);
            if (MODE >= 1) {
                // head of this 8-col group: cols [k0+ac, k0+ac+8) lie in head k0>>4
                int h = k0 >> 4;
                float inv0 = 1.0f / (s0p[(size_t)(m0 + ar) * HDIM + h] + 1e-16f);
                if (MODE == 2) {
                    const float* xp2 = X2 + (size_t)(m0 + ar) * CDIM + k0 + ac;
                    float4 c0 = *(const float4*)(xp2);
                    float4 c1 = *(const float4*)(xp2 + 4);
                    float inv1 = 1.0f / (s1p[(size_t)(m0 + ar) * HDIM + h] + 1e-16f);
                    av0.x = av0.x * inv0 + c0.x * inv1; av0.y = av0.y * inv0 + c0.y * inv1;
                    av0.z = av0.z * inv0 + c0.z * inv1; av0.w = av0.w * inv0 + c0.w * inv1;
                    av1.x = av1.x * inv0 + c1.x * inv1; av1.y = av1.y * inv0 + c1.y * inv1;
                    av1.z = av1.z * inv0 + c1.z * inv1; av1.w = av1.w * inv0 + c1.w * inv1;
                } else {
                    av0.x *= inv0; av0.y *= inv0; av0.z *= inv0; av0.w *= inv0;
                    av1.x *= inv0; av1.y *= inv0; av1.z *= inv0; av1.w *= inv0;
                }
                av0.x = gelu_exact(av0.x); av0.y = gelu_exact(av0.y);
                av0.z = gelu_exact(av0.z); av0.w = gelu_exact(av0.w);
                av1.x = gelu_exact(av1.x); av1.y = gelu_exact(av1.y);
                av1.z = gelu_exact(av1.z); av1.w = gelu_exact(av1.w);
            }
        }
        const float* wp = W + (size_t)(k0 + br) * CDIM + bc;
        float4 bv0 = *(const float4*)(wp);
        float4 bv1 = *(const float4*)(wp + 4);

        As[ac + 0][ar] = av0.x; As[ac + 1][ar] = av0.y;
        As[ac + 2][ar] = av0.z; As[ac + 3][ar] = av0.w;
        As[ac + 4][ar] = av1.x; As[ac + 5][ar] = av1.y;
        As[ac + 6][ar] = av1.z; As[ac + 7][ar] = av1.w;
        *(float4*)(&Bs[br][bc]) = bv0;
        *(float4*)(&Bs[br][bc + 4]) = bv1;
        __syncthreads();
#pragma unroll
        for (int kk = 0; kk < 16; kk++) {
            float a[8], b[8];
            *(float4*)(a)     = *(const float4*)(&As[kk][trow * 4]);
            *(float4*)(a + 4) = *(const float4*)(&As[kk][64 + trow * 4]);
            *(float4*)(b)     = *(const float4*)(&Bs[kk][tcol * 4]);
            *(float4*)(b + 4) = *(const float4*)(&Bs[kk][64 + tcol * 4]);
#pragma unroll
            for (int i = 0; i < 8; i++)
#pragma unroll
                for (int j = 0; j < 8; j++) acc[i][j] += a[i] * b[j];
        }
        __syncthreads();
    }

    float beta = 0.f, ombeta = 0.f;
    if (MODE >= 1) {
        float sv = skipv[tsel];
        beta = 1.0f / (1.0f + __expf(-sv));
        ombeta = 1.0f - beta;
    }
#pragma unroll
    for (int i = 0; i < 8; i++) {
        int m = m0 + ((i < 4) ? (trow * 4 + i) : (64 + trow * 4 + i - 4));
        if (m < M) {
#pragma unroll
            for (int jg = 0; jg < 2; jg++) {
                int col = (jg == 0) ? (tcol * 4) : (64 + tcol * 4);
                int j0 = jg * 4;
                float4 bb = *(const float4*)(bias + col);
                float4 o;
                o.x = acc[i][j0 + 0] + bb.x;
                o.y = acc[i][j0 + 1] + bb.y;
                o.z = acc[i][j0 + 2] + bb.z;
                o.w = acc[i][j0 + 3] + bb.w;
                if (MODE >= 1) {
                    float4 xr = *(const float4*)(Xres + (size_t)m * CDIM + col);
                    o.x = beta * o.x + ombeta * xr.x;
                    o.y = beta * o.y + ombeta * xr.y;
                    o.z = beta * o.z + ombeta * xr.z;
                    o.w = beta * o.w + ombeta * xr.w;
                }
                *(float4*)(Cout + (size_t)m * CDIM + col) = o;
            }
        }
    }
}

// ---------------- fused edge pass: logits -> exp -> UNNORMALIZED scatter -------
// One warp per edge; lane l covers elements [4l, 4l+4), head h = l>>2.
// Softmax max-subtraction skipped (logits are O(1); fp32 exp cannot overflow;
// alpha identical up to rounding). Normalization deferred to epilogue GEMM:
//   sum_e (ev/s)*v == (sum_e ev*v)/s.
__global__ __launch_bounds__(256) void edge_fused_k(
    const int* __restrict__ eidx, int E,
    const float* __restrict__ q, const float* __restrict__ kr,
    const float* __restrict__ vr, const float* __restrict__ prel,
    float* __restrict__ ssum, float* __restrict__ aggR) {
    int gt = blockIdx.x * blockDim.x + threadIdx.x;
    int e = gt >> 5;
    if (e >= E) return;
    int lane = threadIdx.x & 31;
    int h = lane >> 2;
    int src = __ldg(eidx + e);
    int dst = __ldg(eidx + E + e);
    float4 qv = *(const float4*)(q + (size_t)dst * CDIM + lane * 4);
    float4 kv = *(const float4*)(kr + (size_t)src * CDIM + lane * 4);
    float p = qv.x * kv.x + qv.y * kv.y + qv.z * kv.z + qv.w * kv.w;
    p += __shfl_xor_sync(0xffffffffu, p, 1);
    p += __shfl_xor_sync(0xffffffffu, p, 2);   // all 4 lanes of the head hold full dot
    float ev = __expf(p * 0.25f * __ldg(prel + h));   // scale = 1/sqrt(16)
    if ((lane & 3) == 0)
        atomicAdd(ssum + (size_t)dst * HDIM + h, ev);
    float4 v = *(const float4*)(vr + (size_t)src * CDIM + lane * 4);
    float* ap = aggR + (size_t)dst * CDIM + lane * 4;
    // one 128-bit reduction instead of 4 scalar atomics (sm_90+)
    asm volatile("red.global.add.v4.f32 [%0], {%1, %2, %3, %4};"
                 :: "l"(ap), "f"(v.x * ev), "f"(v.y * ev), "f"(v.z * ev), "f"(v.w * ev)
                 : "memory");
}

// ---------------- launch ----------------
extern "C" void kernel_launch(void* const* d_in, const int* in_sizes, int n_in,
                              void* d_out, int out_size) {
    const float* xA = (const float*)d_in[0];
    const float* xB = (const float*)d_in[1];
    const int* eAB = (const int*)d_in[2];
    const int* eBA = (const int*)d_in[3];
    const int* eAA = (const int*)d_in[4];
    const float* Wk = (const float*)d_in[5];
    const float* bk = (const float*)d_in[6];
    const float* Wq = (const float*)d_in[7];
    const float* bq = (const float*)d_in[8];
    const float* Wv = (const float*)d_in[9];
    const float* bv = (const float*)d_in[10];
    const float* Wa = (const float*)d_in[11];
    const float* ba = (const float*)d_in[12];
    const float* skip = (const float*)d_in[13];
    const float* a_rel = (const float*)d_in[14];
    const float* m_rel = (const float*)d_in[15];
    const float* p_rel = (const float*)d_in[16];
    float* out = (float*)d_out;

    int NA = in_sizes[0] / CDIM;
    int NB = in_sizes[1] / CDIM;
    int E0 = in_sizes[2] / 2;
    int E1 = in_sizes[3] / 2;
    int E2 = in_sizes[4] / 2;

    float *qA, *qB, *kr, *vr, *ssum, *aggR, *Wkrp, *Wvrp, *bkrp, *bvrp;
    cudaGetSymbolAddress((void**)&qA, g_qA);
    cudaGetSymbolAddress((void**)&qB, g_qB);
    cudaGetSymbolAddress((void**)&kr, g_kr);
    cudaGetSymbolAddress((void**)&vr, g_vr);
    cudaGetSymbolAddress((void**)&ssum, g_sum);
    cudaGetSymbolAddress((void**)&aggR, g_aggR);
    cudaGetSymbolAddress((void**)&Wkrp, g_Wkr);
    cudaGetSymbolAddress((void**)&Wvrp, g_Wvr);
    cudaGetSymbolAddress((void**)&bkrp, g_bkr);
    cudaGetSymbolAddress((void**)&bvrp, g_bvr);

    // zero the reduction targets
    cudaMemsetAsync(ssum, 0, (size_t)3 * NMAX * HDIM * sizeof(float));
    cudaMemsetAsync(aggR, 0, (size_t)3 * NMAX * CDIM * sizeof(float));

    // fold relation transforms into projection weights
    prep_weights_k<<<dim3(CDIM, 3), CDIM>>>(Wk, bk, Wv, bv, a_rel, m_rel);

    const int CC = CDIM * CDIM;
    const size_t NC = (size_t)NMAX * CDIM;
    const size_t NH = (size_t)NMAX * HDIM;
    dim3 blk(256);
    dim3 gA((NA + 127) / 128), gB((NB + 127) / 128);

    // 8 projection GEMMs (q for both types; kr/vr per relation, relation folded)
    sgemm128_k<0><<<gA, blk>>>(xA, nullptr, nullptr, nullptr, Wq, bq, nullptr, 0, nullptr, qA, NA);
    sgemm128_k<0><<<gB, blk>>>(xB, nullptr, nullptr, nullptr, Wq + CC, bq + CDIM, nullptr, 0, nullptr, qB, NB);
    sgemm128_k<0><<<gA, blk>>>(xA, nullptr, nullptr, nullptr, Wkrp + 0 * CC, bkrp + 0 * CDIM, nullptr, 0, nullptr, kr + 0 * NC, NA);
    sgemm128_k<0><<<gB, blk>>>(xB, nullptr, nullptr, nullptr, Wkrp + 1 * CC, bkrp + 1 * CDIM, nullptr, 0, nullptr, kr + 1 * NC, NB);
    sgemm128_k<0><<<gA, blk>>>(xA, nullptr, nullptr, nullptr, Wkrp + 2 * CC, bkrp + 2 * CDIM, nullptr, 0, nullptr, kr + 2 * NC, NA);
    sgemm128_k<0><<<gA, blk>>>(xA, nullptr, nullptr, nullptr, Wvrp + 0 * CC, bvrp + 0 * CDIM, nullptr, 0, nullptr, vr + 0 * NC, NA);
    sgemm128_k<0><<<gB, blk>>>(xB, nullptr, nullptr, nullptr, Wvrp + 1 * CC, bvrp + 1 * CDIM, nullptr, 0, nullptr, vr + 1 * NC, NB);
    sgemm128_k<0><<<gA, blk>>>(xA, nullptr, nullptr, nullptr, Wvrp + 2 * CC, bvrp + 2 * CDIM, nullptr, 0, nullptr, vr + 2 * NC, NA);

    // fused edge passes (one per relation)
    // r0: A->B, dst type B uses qB; r1: B->A uses qA; r2: A->A uses qA
    edge_fused_k<<<(E0 * 32 + 255) / 256, blk>>>(eAB, E0, qB, kr + 0 * NC, vr + 0 * NC, p_rel + 0,  ssum + 0 * NH, aggR + 0 * NC);
    edge_fused_k<<<(E1 * 32 + 255) / 256, blk>>>(eBA, E1, qA, kr + 1 * NC, vr + 1 * NC, p_rel + 8,  ssum + 1 * NH, aggR + 1 * NC);
    edge_fused_k<<<(E2 * 32 + 255) / 256, blk>>>(eAA, E2, qA, kr + 2 * NC, vr + 2 * NC, p_rel + 16, ssum + 2 * NH, aggR + 2 * NC);

    // epilogue GEMMs with fused normalize+gelu A-load and sigmoid-skip blend
    // type A aggregates relations r1, r2; type B aggregates r0
    sgemm128_k<2><<<gA, blk>>>(aggR + 1 * NC, aggR + 2 * NC, ssum + 1 * NH, ssum + 2 * NH,
                               Wa, ba, skip, 0, xA, out, NA);
    sgemm128_k<1><<<gB, blk>>>(aggR + 0 * NC, nullptr, ssum + 0 * NH, nullptr,
                               Wa + CC, ba + CDIM, skip, 1, xB, out + (size_t)NA * CDIM, NB);
}

// round 13
// speedup vs baseline: 1.6721x; 1.6721x over previous
#include <cuda_runtime.h>
#include <cuda_bf16.h>
#include <math.h>
#include <stdint.h>

#define CDIM 128
#define HDIM 8
#define DDIM 16
#define NMAX 100000
#define EMAX 800000

// ---------------- device scratch (static, no allocations) ----------------
__device__ float g_qA[NMAX * CDIM];
__device__ float g_qB[NMAX * CDIM];
__device__ float g_kr[3][NMAX * CDIM];
__device__ float g_vr[3][NMAX * CDIM];
__device__ float g_sum[3][NMAX * HDIM];   // per-relation segment sums of exp
__device__ float g_aggR[3][NMAX * CDIM];  // per-relation UNNORMALIZED sum(ev*vr)
__device__ float g_Wkr[3][CDIM * CDIM];
__device__ float g_Wvr[3][CDIM * CDIM];
__device__ float g_bkr[3][CDIM];
__device__ float g_bvr[3][CDIM];
// bf16 split storage: 10 transposed weight matrices [cout][cin], hi+lo
__device__ __nv_bfloat16 g_WTh[10 * CDIM * CDIM];
__device__ __nv_bfloat16 g_WTl[10 * CDIM * CDIM];
// bf16 split node features (reused as gelu-activation buffers for the epilogue)
__device__ __nv_bfloat16 g_xAh[NMAX * CDIM];
__device__ __nv_bfloat16 g_xAl[NMAX * CDIM];
__device__ __nv_bfloat16 g_xBh[NMAX * CDIM];
__device__ __nv_bfloat16 g_xBl[NMAX * CDIM];

// ---------------- fold a_rel/m_rel into projection weights ----------------
__global__ void prep_weights_k(const float* __restrict__ Wk, const float* __restrict__ bk,
                               const float* __restrict__ Wv, const float* __restrict__ bv,
                               const float* __restrict__ a_rel, const float* __restrict__ m_rel) {
    int r = blockIdx.y;
    int cin = blockIdx.x;
    int j = threadIdx.x;
    int s = (r == 1) ? 1 : 0;
    int h = j >> 4, e = j & 15;
    const float* wkrow = Wk + s * CDIM * CDIM + cin * CDIM + h * DDIM;
    const float* wvrow = Wv + s * CDIM * CDIM + cin * CDIM + h * DDIM;
    const float* ar = a_rel + ((r * HDIM + h) * DDIM) * DDIM + e;
    const float* mr = m_rel + ((r * HDIM + h) * DDIM) * DDIM + e;
    float sk = 0.f, sv = 0.f;
#pragma unroll
    for (int d = 0; d < DDIM; d++) {
        sk += wkrow[d] * ar[d * DDIM];
        sv += wvrow[d] * mr[d * DDIM];
    }
    g_Wkr[r][cin * CDIM + j] = sk;
    g_Wvr[r][cin * CDIM + j] = sv;
    if (cin == 0) {
        const float* bkrow = bk + s * CDIM + h * DDIM;
        const float* bvrow = bv + s * CDIM + h * DDIM;
        float tk = 0.f, tv = 0.f;
#pragma unroll
        for (int d = 0; d < DDIM; d++) {
            tk += bkrow[d] * ar[d * DDIM];
            tv += bvrow[d] * mr[d * DDIM];
        }
        g_bkr[r][j] = tk;
        g_bvr[r][j] = tv;
    }
}

// ------- transpose + split-convert the 10 weight matrices to bf16 hi/lo -------
__global__ void wcvt_k(const float* __restrict__ Wq, const float* __restrict__ Wa) {
    int mi = blockIdx.x;
    const float* src;
    if (mi == 0) src = Wq;
    else if (mi == 1) src = Wq + CDIM * CDIM;
    else if (mi <= 4) src = g_Wkr[mi - 2];
    else if (mi <= 7) src = g_Wvr[mi - 5];
    else if (mi == 8) src = Wa;
    else src = Wa + CDIM * CDIM;
    __nv_bfloat16* dh = g_WTh + mi * CDIM * CDIM;
    __nv_bfloat16* dl = g_WTl + mi * CDIM * CDIM;
    for (int idx = threadIdx.x; idx < CDIM * CDIM; idx += blockDim.x) {
        int k = idx >> 7, n = idx & 127;
        float v = src[k * CDIM + n];
        __nv_bfloat16 h = __float2bfloat16(v);
        dh[n * CDIM + k] = h;
        dl[n * CDIM + k] = __float2bfloat16(v - __bfloat162float(h));
    }
}

// ---------------- elementwise split-convert x -> bf16 hi/lo ----------------
__global__ void cvt_k(const float* __restrict__ X, __nv_bfloat16* __restrict__ H,
                      __nv_bfloat16* __restrict__ L, int n4) {
    int i = blockIdx.x * blockDim.x + threadIdx.x;
    if (i >= n4) return;
    float4 v = *(const float4*)(X + (size_t)i * 4);
    __nv_bfloat16 h0 = __float2bfloat16(v.x), h1 = __float2bfloat16(v.y);
    __nv_bfloat16 h2 = __float2bfloat16(v.z), h3 = __float2bfloat16(v.w);
    __nv_bfloat16 l0 = __float2bfloat16(v.x - __bfloat162float(h0));
    __nv_bfloat16 l1 = __float2bfloat16(v.y - __bfloat162float(h1));
    __nv_bfloat16 l2 = __float2bfloat16(v.z - __bfloat162float(h2));
    __nv_bfloat16 l3 = __float2bfloat16(v.w - __bfloat162float(h3));
    __nv_bfloat162* Hp = (__nv_bfloat162*)(H + (size_t)i * 4);
    __nv_bfloat162* Lp = (__nv_bfloat162*)(L + (size_t)i * 4);
    Hp[0] = __halves2bfloat162(h0, h1); Hp[1] = __halves2bfloat162(h2, h3);
    Lp[0] = __halves2bfloat162(l0, l1); Lp[1] = __halves2bfloat162(l2, l3);
}

// ------- epilogue pre-pass: G = gelu(agg0/s0 [+ agg1/s1]) -> bf16 hi/lo -------
__device__ __forceinline__ float gelu_exact(float x) {
    return 0.5f * x * (1.0f + erff(x * 0.70710678118654752f));
}
__global__ void geluprep_k(const float* __restrict__ A0, const float* __restrict__ A1,
                           const float* __restrict__ s0, const float* __restrict__ s1,
                           __nv_bfloat16* __restrict__ H, __nv_bfloat16* __restrict__ L, int M) {
    int i = blockIdx.x * blockDim.x + threadIdx.x;
    if (i >= M * 32) return;
    int m = i >> 5, q = i & 31, h = q >> 2;
    float4 v = *(const float4*)(A0 + (size_t)m * CDIM + q * 4);
    float inv0 = 1.0f / (__ldg(s0 + (size_t)m * HDIM + h) + 1e-16f);
    float x0 = v.x * inv0, x1 = v.y * inv0, x2 = v.z * inv0, x3 = v.w * inv0;
    if (A1) {
        float4 w = *(const float4*)(A1 + (size_t)m * CDIM + q * 4);
        float inv1 = 1.0f / (__ldg(s1 + (size_t)m * HDIM + h) + 1e-16f);
        x0 += w.x * inv1; x1 += w.y * inv1; x2 += w.z * inv1; x3 += w.w * inv1;
    }
    x0 = gelu_exact(x0); x1 = gelu_exact(x1); x2 = gelu_exact(x2); x3 = gelu_exact(x3);
    __nv_bfloat16 h0 = __float2bfloat16(x0), h1 = __float2bfloat16(x1);
    __nv_bfloat16 h2 = __float2bfloat16(x2), h3 = __float2bfloat16(x3);
    __nv_bfloat16 l0 = __float2bfloat16(x0 - __bfloat162float(h0));
    __nv_bfloat16 l1 = __float2bfloat16(x1 - __bfloat162float(h1));
    __nv_bfloat16 l2 = __float2bfloat16(x2 - __bfloat162float(h2));
    __nv_bfloat16 l3 = __float2bfloat16(x3 - __bfloat162float(h3));
    __nv_bfloat162* Hp = (__nv_bfloat162*)(H + (size_t)i * 4);
    __nv_bfloat162* Lp = (__nv_bfloat162*)(L + (size_t)i * 4);
    Hp[0] = __halves2bfloat162(h0, h1); Hp[1] = __halves2bfloat162(h2, h3);
    Lp[0] = __halves2bfloat162(l0, l1); Lp[1] = __halves2bfloat162(l2, l3);
}

// ====== mma.sync split-bf16 GEMM: C[M,128] = A[M,128] @ W + b (base ISA) ======
// D = Ah*Bh + Ah*Bl + Al*Bh via mma.sync.aligned.m16n8k16.row.col.f32.bf16.
// B = W^T stored [n][k] row-major (so row.col layout maps directly).
// SMEM: 4 padded tiles (Ah, Al, Bh, Bl), 128 rows x 136 bf16 (272B rows; the
// 8-short pad makes fragment LDS conflict-free: bank = 4g+t, all distinct).
#define ROWB 272                       // bytes per padded smem row
#define ROWW 68                        // 32-bit words per padded smem row
#define MATB (128 * ROWB)              // 34816 bytes per tile
#define GSM_TOTAL (4 * MATB)           // 139264 bytes

__device__ __forceinline__ void mma16816(float* c, const uint32_t* a, const uint32_t* b) {
    asm volatile(
        "mma.sync.aligned.m16n8k16.row.col.f32.bf16.bf16.f32 "
        "{%0,%1,%2,%3}, {%4,%5,%6,%7}, {%8,%9}, {%0,%1,%2,%3};"
        : "+f"(c[0]), "+f"(c[1]), "+f"(c[2]), "+f"(c[3])
        : "r"(a[0]), "r"(a[1]), "r"(a[2]), "r"(a[3]), "r"(b[0]), "r"(b[1]));
}

template <int MODE>
__global__ __launch_bounds__(256) void hgemm128_k(
    const __nv_bfloat16* __restrict__ Ah, const __nv_bfloat16* __restrict__ Al,
    const __nv_bfloat16* __restrict__ Bh, const __nv_bfloat16* __restrict__ Bl,
    const float* __restrict__ bias, const float* __restrict__ skipv, int tsel,
    const float* __restrict__ Xres, float* __restrict__ Cout, int M) {
    extern __shared__ char smem[];
    int tid = threadIdx.x;
    int wid = tid >> 5, lane = tid & 31;
    int m0 = blockIdx.x * 128;

    // ---- fill 4 padded SMEM tiles: 8192 16B chunks ----
#pragma unroll 8
    for (int i = 0; i < 32; i++) {
        int cid = tid + i * 256;
        int mat = cid >> 11;        // 0=Ah 1=Al 2=Bh 3=Bl
        int rem = cid & 2047;
        int row = rem >> 4;         // 0..127
        int c = rem & 15;           // 16B chunk (8 bf16)
        const __nv_bfloat16* s = (mat < 2) ? ((mat == 0) ? Ah : Al) : ((mat == 2) ? Bh : Bl);
        uint4 val = make_uint4(0u, 0u, 0u, 0u);
        int grow = (mat < 2) ? (m0 + row) : row;
        if (mat >= 2 || grow < M)
            val = *(const uint4*)(s + (size_t)grow * CDIM + c * 8);
        *(uint4*)(smem + mat * MATB + row * ROWB + c * 16) = val;
    }
    __syncthreads();

    const uint32_t* Ash = (const uint32_t*)(smem + 0 * MATB);
    const uint32_t* Asl = (const uint32_t*)(smem + 1 * MATB);
    const uint32_t* Bsh = (const uint32_t*)(smem + 2 * MATB);
    const uint32_t* Bsl = (const uint32_t*)(smem + 3 * MATB);

    int wr = wid >> 2;          // warp row 0..1 -> rows wr*64..+63
    int wc = wid & 3;           // warp col 0..3 -> cols wc*32..+31
    int g = lane >> 2, t = lane & 3;

    float acc[4][4][4];
#pragma unroll
    for (int a = 0; a < 4; a++)
#pragma unroll
        for (int b = 0; b < 4; b++)
#pragma unroll
            for (int c = 0; c < 4; c++) acc[a][b][c] = 0.f;

#pragma unroll
    for (int ks = 0; ks < 8; ks++) {
        int kw = ks * 8;        // word offset of this k16 chunk
        uint32_t ah[4][4], al[4][4], bh[4][2], bl[4][2];
#pragma unroll
        for (int mt = 0; mt < 4; mt++) {
            int r0 = (wr * 64 + mt * 16 + g) * ROWW + kw + t;
            int r1 = r0 + 8 * ROWW;
            ah[mt][0] = Ash[r0];     ah[mt][1] = Ash[r1];
            ah[mt][2] = Ash[r0 + 4]; ah[mt][3] = Ash[r1 + 4];
            al[mt][0] = Asl[r0];     al[mt][1] = Asl[r1];
            al[mt][2] = Asl[r0 + 4]; al[mt][3] = Asl[r1 + 4];
        }
#pragma unroll
        for (int nt = 0; nt < 4; nt++) {
            int n0 = (wc * 32 + nt * 8 + g) * ROWW + kw + t;
            bh[nt][0] = Bsh[n0]; bh[nt][1] = Bsh[n0 + 4];
            bl[nt][0] = Bsl[n0]; bl[nt][1] = Bsl[n0 + 4];
        }
#pragma unroll
        for (int mt = 0; mt < 4; mt++)
#pragma unroll
            for (int nt = 0; nt < 4; nt++) {
                mma16816(acc[mt][nt], ah[mt], bh[nt]);
                mma16816(acc[mt][nt], ah[mt], bl[nt]);
                mma16816(acc[mt][nt], al[mt], bh[nt]);
            }
    }

    // ---- epilogue: D fragment d0=C[g][2t] d1=C[g][2t+1] d2=C[g+8][2t] d3=... ----
    float beta = 0.f, omb = 0.f;
    if (MODE == 1) {
        float sv = __ldg(skipv + tsel);
        beta = 1.0f / (1.0f + __expf(-sv));
        omb = 1.0f - beta;
    }
#pragma unroll
    for (int mt = 0; mt < 4; mt++) {
        int row0 = m0 + wr * 64 + mt * 16 + g;
        int row1 = row0 + 8;
#pragma unroll
        for (int nt = 0; nt < 4; nt++) {
            int col = wc * 32 + nt * 8 + 2 * t;
            float b0 = __ldg(bias + col), b1 = __ldg(bias + col + 1);
            if (row0 < M) {
                float2 o;
                o.x = acc[mt][nt][0] + b0;
                o.y = acc[mt][nt][1] + b1;
                if (MODE == 1) {
                    float2 xr = *(const float2*)(Xres + (size_t)row0 * CDIM + col);
                    o.x = beta * o.x + omb * xr.x;
                    o.y = beta * o.y + omb * xr.y;
                }
                *(float2*)(Cout + (size_t)row0 * CDIM + col) = o;
            }
            if (row1 < M) {
                float2 o;
                o.x = acc[mt][nt][2] + b0;
                o.y = acc[mt][nt][3] + b1;
                if (MODE == 1) {
                    float2 xr = *(const float2*)(Xres + (size_t)row1 * CDIM + col);
                    o.x = beta * o.x + omb * xr.x;
                    o.y = beta * o.y + omb * xr.y;
                }
                *(float2*)(Cout + (size_t)row1 * CDIM + col) = o;
            }
        }
    }
}

// ---------------- fused edge pass (validated on HW in R3) ----------------
__global__ __launch_bounds__(256) void edge_fused_k(
    const int* __restrict__ eidx, int E,
    const float* __restrict__ q, const float* __restrict__ kr,
    const float* __restrict__ vr, const float* __restrict__ prel,
    float* __restrict__ ssum, float* __restrict__ aggR) {
    int gt = blockIdx.x * blockDim.x + threadIdx.x;
    int e = gt >> 5;
    if (e >= E) return;
    int lane = threadIdx.x & 31;
    int h = lane >> 2;
    int src = __ldg(eidx + e);
    int dst = __ldg(eidx + E + e);
    float4 qv = *(const float4*)(q + (size_t)dst * CDIM + lane * 4);
    float4 kv = *(const float4*)(kr + (size_t)src * CDIM + lane * 4);
    float p = qv.x * kv.x + qv.y * kv.y + qv.z * kv.z + qv.w * kv.w;
    p += __shfl_xor_sync(0xffffffffu, p, 1);
    p += __shfl_xor_sync(0xffffffffu, p, 2);
    float ev = __expf(p * 0.25f * __ldg(prel + h));
    if ((lane & 3) == 0)
        atomicAdd(ssum + (size_t)dst * HDIM + h, ev);
    float4 v = *(const float4*)(vr + (size_t)src * CDIM + lane * 4);
    float* ap = aggR + (size_t)dst * CDIM + lane * 4;
    asm volatile("red.global.add.v4.f32 [%0], {%1, %2, %3, %4};"
                 :: "l"(ap), "f"(v.x * ev), "f"(v.y * ev), "f"(v.z * ev), "f"(v.w * ev)
                 : "memory");
}

// ---------------- launch ----------------
extern "C" void kernel_launch(void* const* d_in, const int* in_sizes, int n_in,
                              void* d_out, int out_size) {
    const float* xA = (const float*)d_in[0];
    const float* xB = (const float*)d_in[1];
    const int* eAB = (const int*)d_in[2];
    const int* eBA = (const int*)d_in[3];
    const int* eAA = (const int*)d_in[4];
    const float* Wk = (const float*)d_in[5];
    const float* bk = (const float*)d_in[6];
    const float* Wq = (const float*)d_in[7];
    const float* bq = (const float*)d_in[8];
    const float* Wv = (const float*)d_in[9];
    const float* bv = (const float*)d_in[10];
    const float* Wa = (const float*)d_in[11];
    const float* ba = (const float*)d_in[12];
    const float* skip = (const float*)d_in[13];
    const float* a_rel = (const float*)d_in[14];
    const float* m_rel = (const float*)d_in[15];
    const float* p_rel = (const float*)d_in[16];
    float* out = (float*)d_out;

    int NA = in_sizes[0] / CDIM;
    int NB = in_sizes[1] / CDIM;
    int E0 = in_sizes[2] / 2;
    int E1 = in_sizes[3] / 2;
    int E2 = in_sizes[4] / 2;

    float *qA, *qB, *kr, *vr, *ssum, *aggR, *bkrp, *bvrp;
    __nv_bfloat16 *WTh, *WTl, *xAh, *xAl, *xBh, *xBl;
    cudaGetSymbolAddress((void**)&qA, g_qA);
    cudaGetSymbolAddress((void**)&qB, g_qB);
    cudaGetSymbolAddress((void**)&kr, g_kr);
    cudaGetSymbolAddress((void**)&vr, g_vr);
    cudaGetSymbolAddress((void**)&ssum, g_sum);
    cudaGetSymbolAddress((void**)&aggR, g_aggR);
    cudaGetSymbolAddress((void**)&bkrp, g_bkr);
    cudaGetSymbolAddress((void**)&bvrp, g_bvr);
    cudaGetSymbolAddress((void**)&WTh, g_WTh);
    cudaGetSymbolAddress((void**)&WTl, g_WTl);
    cudaGetSymbolAddress((void**)&xAh, g_xAh);
    cudaGetSymbolAddress((void**)&xAl, g_xAl);
    cudaGetSymbolAddress((void**)&xBh, g_xBh);
    cudaGetSymbolAddress((void**)&xBl, g_xBl);

    cudaFuncSetAttribute(hgemm128_k<0>, cudaFuncAttributeMaxDynamicSharedMemorySize, GSM_TOTAL);
    cudaFuncSetAttribute(hgemm128_k<1>, cudaFuncAttributeMaxDynamicSharedMemorySize, GSM_TOTAL);

    cudaMemsetAsync(ssum, 0, (size_t)3 * NMAX * HDIM * sizeof(float));
    cudaMemsetAsync(aggR, 0, (size_t)3 * NMAX * CDIM * sizeof(float));

    prep_weights_k<<<dim3(CDIM, 3), CDIM>>>(Wk, bk, Wv, bv, a_rel, m_rel);
    wcvt_k<<<10, 256>>>(Wq, Wa);
    cvt_k<<<(NA * 32 + 255) / 256, 256>>>(xA, xAh, xAl, NA * 32);
    cvt_k<<<(NB * 32 + 255) / 256, 256>>>(xB, xBh, xBl, NB * 32);

    const int CC = CDIM * CDIM;
    const size_t NC = (size_t)NMAX * CDIM;
    const size_t NH = (size_t)NMAX * HDIM;
    dim3 gA((NA + 127) / 128), gB((NB + 127) / 128);

    // 8 projection GEMMs (split-bf16 mma.sync)
    hgemm128_k<0><<<gA, 256, GSM_TOTAL>>>(xAh, xAl, WTh + 0 * CC, WTl + 0 * CC, bq, nullptr, 0, nullptr, qA, NA);
    hgemm128_k<0><<<gB, 256, GSM_TOTAL>>>(xBh, xBl, WTh + 1 * CC, WTl + 1 * CC, bq + CDIM, nullptr, 0, nullptr, qB, NB);
    hgemm128_k<0><<<gA, 256, GSM_TOTAL>>>(xAh, xAl, WTh + 2 * CC, WTl + 2 * CC, bkrp + 0 * CDIM, nullptr, 0, nullptr, kr + 0 * NC, NA);
    hgemm128_k<0><<<gB, 256, GSM_TOTAL>>>(xBh, xBl, WTh + 3 * CC, WTl + 3 * CC, bkrp + 1 * CDIM, nullptr, 0, nullptr, kr + 1 * NC, NB);
    hgemm128_k<0><<<gA, 256, GSM_TOTAL>>>(xAh, xAl, WTh + 4 * CC, WTl + 4 * CC, bkrp + 2 * CDIM, nullptr, 0, nullptr, kr + 2 * NC, NA);
    hgemm128_k<0><<<gA, 256, GSM_TOTAL>>>(xAh, xAl, WTh + 5 * CC, WTl + 5 * CC, bvrp + 0 * CDIM, nullptr, 0, nullptr, vr + 0 * NC, NA);
    hgemm128_k<0><<<gB, 256, GSM_TOTAL>>>(xBh, xBl, WTh + 6 * CC, WTl + 6 * CC, bvrp + 1 * CDIM, nullptr, 0, nullptr, vr + 1 * NC, NB);
    hgemm128_k<0><<<gA, 256, GSM_TOTAL>>>(xAh, xAl, WTh + 7 * CC, WTl + 7 * CC, bvrp + 2 * CDIM, nullptr, 0, nullptr, vr + 2 * NC, NA);

    // fused edge passes
    edge_fused_k<<<(E0 * 32 + 255) / 256, 256>>>(eAB, E0, qB, kr + 0 * NC, vr + 0 * NC, p_rel + 0,  ssum + 0 * NH, aggR + 0 * NC);
    edge_fused_k<<<(E1 * 32 + 255) / 256, 256>>>(eBA, E1, qA, kr + 1 * NC, vr + 1 * NC, p_rel + 8,  ssum + 1 * NH, aggR + 1 * NC);
    edge_fused_k<<<(E2 * 32 + 255) / 256, 256>>>(eAA, E2, qA, kr + 2 * NC, vr + 2 * NC, p_rel + 16, ssum + 2 * NH, aggR + 2 * NC);

    // epilogue: normalize+gelu pre-pass into bf16 hi/lo (reuse x buffers), then GEMM+blend
    geluprep_k<<<(NA * 32 + 255) / 256, 256>>>(aggR + 1 * NC, aggR + 2 * NC, ssum + 1 * NH, ssum + 2 * NH, xAh, xAl, NA);
    geluprep_k<<<(NB * 32 + 255) / 256, 256>>>(aggR + 0 * NC, nullptr, ssum + 0 * NH, nullptr, xBh, xBl, NB);
    hgemm128_k<1><<<gA, 256, GSM_TOTAL>>>(xAh, xAl, WTh + 8 * CC, WTl + 8 * CC, ba, skip, 0, xA, out, NA);
    hgemm128_k<1><<<gB, 256, GSM_TOTAL>>>(xBh, xBl, WTh + 9 * CC, WTl + 9 * CC, ba + CDIM, skip, 1, xB, out + (size_t)NA * CDIM, NB);
}

// round 16
// speedup vs baseline: 1.7959x; 1.0740x over previous
#include <cuda_runtime.h>
#include <cuda_bf16.h>
#include <math.h>
#include <stdint.h>

#define CDIM 128
#define HDIM 8
#define DDIM 16
#define NMAX 100000
#define EMAX 800000
#define LDA 640   // projA row: q|kr0|kr2|vr0|vr2
#define LDB 384   // projB row: q|kr1|vr1

// ---------------- device scratch (static, no allocations) ----------------
__device__ float g_projA[NMAX * LDA];
__device__ float g_projB[NMAX * LDB];
__device__ float g_sum[3][NMAX * HDIM];   // per-relation segment sums of exp
__device__ float g_aggR[3][NMAX * CDIM];  // per-relation UNNORMALIZED sum(ev*vr)
__device__ float g_Wkr[3][CDIM * CDIM];
__device__ float g_Wvr[3][CDIM * CDIM];
__device__ float g_bkr[3][CDIM];
__device__ float g_bvr[3][CDIM];
__device__ float g_biasA[LDA];
__device__ float g_biasB[LDB];
// bf16 split storage: 10 transposed weight matrices [cout][cin], hi+lo
// order: 0 Wq(A) | 1 Wkr0 | 2 Wkr2 | 3 Wvr0 | 4 Wvr2 | 5 Wq(B) | 6 Wkr1 | 7 Wvr1 | 8 Wa(A) | 9 Wa(B)
__device__ __nv_bfloat16 g_WTh[10 * CDIM * CDIM];
__device__ __nv_bfloat16 g_WTl[10 * CDIM * CDIM];
// bf16 split node features (reused as gelu-activation buffers for the epilogue)
__device__ __nv_bfloat16 g_xAh[NMAX * CDIM];
__device__ __nv_bfloat16 g_xAl[NMAX * CDIM];
__device__ __nv_bfloat16 g_xBh[NMAX * CDIM];
__device__ __nv_bfloat16 g_xBl[NMAX * CDIM];

// ---------------- fold a_rel/m_rel into projection weights ----------------
__global__ void prep_weights_k(const float* __restrict__ Wk, const float* __restrict__ bk,
                               const float* __restrict__ Wv, const float* __restrict__ bv,
                               const float* __restrict__ a_rel, const float* __restrict__ m_rel) {
    int r = blockIdx.y;
    int cin = blockIdx.x;
    int j = threadIdx.x;
    int s = (r == 1) ? 1 : 0;
    int h = j >> 4, e = j & 15;
    const float* wkrow = Wk + s * CDIM * CDIM + cin * CDIM + h * DDIM;
    const float* wvrow = Wv + s * CDIM * CDIM + cin * CDIM + h * DDIM;
    const float* ar = a_rel + ((r * HDIM + h) * DDIM) * DDIM + e;
    const float* mr = m_rel + ((r * HDIM + h) * DDIM) * DDIM + e;
    float sk = 0.f, sv = 0.f;
#pragma unroll
    for (int d = 0; d < DDIM; d++) {
        sk += wkrow[d] * ar[d * DDIM];
        sv += wvrow[d] * mr[d * DDIM];
    }
    g_Wkr[r][cin * CDIM + j] = sk;
    g_Wvr[r][cin * CDIM + j] = sv;
    if (cin == 0) {
        const float* bkrow = bk + s * CDIM + h * DDIM;
        const float* bvrow = bv + s * CDIM + h * DDIM;
        float tk = 0.f, tv = 0.f;
#pragma unroll
        for (int d = 0; d < DDIM; d++) {
            tk += bkrow[d] * ar[d * DDIM];
            tv += bvrow[d] * mr[d * DDIM];
        }
        g_bkr[r][j] = tk;
        g_bvr[r][j] = tv;
    }
}

// ---------------- concat biases into wide-GEMM order ----------------
__global__ void biascat_k(const float* __restrict__ bq) {
    int t = blockIdx.x * blockDim.x + threadIdx.x;
    if (t < LDA) {
        int c = t >> 7, off = t & 127;
        float v;
        if (c == 0) v = bq[off];
        else if (c == 1) v = g_bkr[0][off];
        else if (c == 2) v = g_bkr[2][off];
        else if (c == 3) v = g_bvr[0][off];
        else v = g_bvr[2][off];
        g_biasA[t] = v;
    } else if (t < LDA + LDB) {
        int u = t - LDA;
        int c = u >> 7, off = u & 127;
        float v;
        if (c == 0) v = bq[CDIM + off];
        else if (c == 1) v = g_bkr[1][off];
        else v = g_bvr[1][off];
        g_biasB[u] = v;
    }
}

// ------- transpose + split-convert the 10 weight matrices to bf16 hi/lo -------
__global__ void wcvt_k(const float* __restrict__ Wq, const float* __restrict__ Wa) {
    int mi = blockIdx.x;
    const float* src;
    if (mi == 0) src = Wq;
    else if (mi == 1) src = g_Wkr[0];
    else if (mi == 2) src = g_Wkr[2];
    else if (mi == 3) src = g_Wvr[0];
    else if (mi == 4) src = g_Wvr[2];
    else if (mi == 5) src = Wq + CDIM * CDIM;
    else if (mi == 6) src = g_Wkr[1];
    else if (mi == 7) src = g_Wvr[1];
    else if (mi == 8) src = Wa;
    else src = Wa + CDIM * CDIM;
    __nv_bfloat16* dh = g_WTh + mi * CDIM * CDIM;
    __nv_bfloat16* dl = g_WTl + mi * CDIM * CDIM;
    for (int idx = threadIdx.x; idx < CDIM * CDIM; idx += blockDim.x) {
        int k = idx >> 7, n = idx & 127;
        float v = src[k * CDIM + n];
        __nv_bfloat16 h = __float2bfloat16(v);
        dh[n * CDIM + k] = h;
        dl[n * CDIM + k] = __float2bfloat16(v - __bfloat162float(h));
    }
}

// ---------------- elementwise split-convert x -> bf16 hi/lo ----------------
__global__ void cvt_k(const float* __restrict__ X, __nv_bfloat16* __restrict__ H,
                      __nv_bfloat16* __restrict__ L, int n4) {
    int i = blockIdx.x * blockDim.x + threadIdx.x;
    if (i >= n4) return;
    float4 v = *(const float4*)(X + (size_t)i * 4);
    __nv_bfloat16 h0 = __float2bfloat16(v.x), h1 = __float2bfloat16(v.y);
    __nv_bfloat16 h2 = __float2bfloat16(v.z), h3 = __float2bfloat16(v.w);
    __nv_bfloat16 l0 = __float2bfloat16(v.x - __bfloat162float(h0));
    __nv_bfloat16 l1 = __float2bfloat16(v.y - __bfloat162float(h1));
    __nv_bfloat16 l2 = __float2bfloat16(v.z - __bfloat162float(h2));
    __nv_bfloat16 l3 = __float2bfloat16(v.w - __bfloat162float(h3));
    __nv_bfloat162* Hp = (__nv_bfloat162*)(H + (size_t)i * 4);
    __nv_bfloat162* Lp = (__nv_bfloat162*)(L + (size_t)i * 4);
    Hp[0] = __halves2bfloat162(h0, h1); Hp[1] = __halves2bfloat162(h2, h3);
    Lp[0] = __halves2bfloat162(l0, l1); Lp[1] = __halves2bfloat162(l2, l3);
}

// ------- epilogue pre-pass: G = gelu(agg0/s0 [+ agg1/s1]) -> bf16 hi/lo -------
__device__ __forceinline__ float gelu_exact(float x) {
    return 0.5f * x * (1.0f + erff(x * 0.70710678118654752f));
}
__global__ void geluprep_k(const float* __restrict__ A0, const float* __restrict__ A1,
                           const float* __restrict__ s0, const float* __restrict__ s1,
                           __nv_bfloat16* __restrict__ H, __nv_bfloat16* __restrict__ L, int M) {
    int i = blockIdx.x * blockDim.x + threadIdx.x;
    if (i >= M * 32) return;
    int m = i >> 5, q = i & 31, h = q >> 2;
    float4 v = *(const float4*)(A0 + (size_t)m * CDIM + q * 4);
    float inv0 = 1.0f / (__ldg(s0 + (size_t)m * HDIM + h) + 1e-16f);
    float x0 = v.x * inv0, x1 = v.y * inv0, x2 = v.z * inv0, x3 = v.w * inv0;
    if (A1) {
        float4 w = *(const float4*)(A1 + (size_t)m * CDIM + q * 4);
        float inv1 = 1.0f / (__ldg(s1 + (size_t)m * HDIM + h) + 1e-16f);
        x0 += w.x * inv1; x1 += w.y * inv1; x2 += w.z * inv1; x3 += w.w * inv1;
    }
    x0 = gelu_exact(x0); x1 = gelu_exact(x1); x2 = gelu_exact(x2); x3 = gelu_exact(x3);
    __nv_bfloat16 h0 = __float2bfloat16(x0), h1 = __float2bfloat16(x1);
    __nv_bfloat16 h2 = __float2bfloat16(x2), h3 = __float2bfloat16(x3);
    __nv_bfloat16 l0 = __float2bfloat16(x0 - __bfloat162float(h0));
    __nv_bfloat16 l1 = __float2bfloat16(x1 - __bfloat162float(h1));
    __nv_bfloat16 l2 = __float2bfloat16(x2 - __bfloat162float(h2));
    __nv_bfloat16 l3 = __float2bfloat16(x3 - __bfloat162float(h3));
    __nv_bfloat162* Hp = (__nv_bfloat162*)(H + (size_t)i * 4);
    __nv_bfloat162* Lp = (__nv_bfloat162*)(L + (size_t)i * 4);
    Hp[0] = __halves2bfloat162(h0, h1); Hp[1] = __halves2bfloat162(h2, h3);
    Lp[0] = __halves2bfloat162(l0, l1); Lp[1] = __halves2bfloat162(l2, l3);
}

// ====== mma.sync split-bf16 GEMM: C[M, NCHUNK*128] = A[M,128] @ [W_c] + b ======
// A (hi+lo) staged once in smem; B chunks looped. Padded rows for bank-free LDS.
#define ROWB 272
#define ROWW 68
#define MATB (128 * ROWB)
#define GSM_TOTAL (4 * MATB)

__device__ __forceinline__ void mma16816(float* c, const uint32_t* a, const uint32_t* b) {
    asm volatile(
        "mma.sync.aligned.m16n8k16.row.col.f32.bf16.bf16.f32 "
        "{%0,%1,%2,%3}, {%4,%5,%6,%7}, {%8,%9}, {%0,%1,%2,%3};"
        : "+f"(c[0]), "+f"(c[1]), "+f"(c[2]), "+f"(c[3])
        : "r"(a[0]), "r"(a[1]), "r"(a[2]), "r"(a[3]), "r"(b[0]), "r"(b[1]));
}

template <int NCHUNK, int MODE>
__global__ __launch_bounds__(256) void hgemm_multi_k(
    const __nv_bfloat16* __restrict__ Ah, const __nv_bfloat16* __restrict__ Al,
    const __nv_bfloat16* __restrict__ BhB, const __nv_bfloat16* __restrict__ BlB,
    const float* __restrict__ bias, const float* __restrict__ skipv, int tsel,
    const float* __restrict__ Xres, float* __restrict__ Cout, int ldc, int M) {
    extern __shared__ char smem[];
    int tid = threadIdx.x;
    int wid = tid >> 5, lane = tid & 31;
    int m0 = blockIdx.x * 128;

    // ---- stage A (hi+lo) once ----
#pragma unroll 4
    for (int i = 0; i < 16; i++) {
        int cid = tid + i * 256;
        int mat = cid >> 11;        // 0=Ah 1=Al
        int rem = cid & 2047;
        int row = rem >> 4;
        int c = rem & 15;
        const __nv_bfloat16* s = (mat == 0) ? Ah : Al;
        uint4 val = make_uint4(0u, 0u, 0u, 0u);
        int grow = m0 + row;
        if (grow < M) val = *(const uint4*)(s + (size_t)grow * CDIM + c * 8);
        *(uint4*)(smem + mat * MATB + row * ROWB + c * 16) = val;
    }

    const uint32_t* Ash = (const uint32_t*)(smem + 0 * MATB);
    const uint32_t* Asl = (const uint32_t*)(smem + 1 * MATB);
    const uint32_t* Bsh = (const uint32_t*)(smem + 2 * MATB);
    const uint32_t* Bsl = (const uint32_t*)(smem + 3 * MATB);

    int wr = wid >> 2, wc = wid & 3;
    int g = lane >> 2, t = lane & 3;

    float beta = 0.f, omb = 0.f;
    if (MODE == 1) {
        float sv = __ldg(skipv + tsel);
        beta = 1.0f / (1.0f + __expf(-sv));
        omb = 1.0f - beta;
    }

    for (int ch = 0; ch < NCHUNK; ch++) {
        // ---- stage B chunk (hi+lo) ----
#pragma unroll 4
        for (int i = 0; i < 16; i++) {
            int cid = tid + i * 256;
            int mat = cid >> 11;    // 0=Bh 1=Bl
            int rem = cid & 2047;
            int row = rem >> 4;
            int c = rem & 15;
            const __nv_bfloat16* s = ((mat == 0) ? BhB : BlB) + (size_t)ch * CDIM * CDIM;
            uint4 val = *(const uint4*)(s + (size_t)row * CDIM + c * 8);
            *(uint4*)(smem + (2 + mat) * MATB + row * ROWB + c * 16) = val;
        }
        __syncthreads();

        float acc[4][4][4];
#pragma unroll
        for (int a = 0; a < 4; a++)
#pragma unroll
            for (int b = 0; b < 4; b++)
#pragma unroll
                for (int c = 0; c < 4; c++) acc[a][b][c] = 0.f;

#pragma unroll
        for (int ks = 0; ks < 8; ks++) {
            int kw = ks * 8;
            uint32_t ah[4][4], al[4][4], bh[4][2], bl[4][2];
#pragma unroll
            for (int mt = 0; mt < 4; mt++) {
                int r0 = (wr * 64 + mt * 16 + g) * ROWW + kw + t;
                int r1 = r0 + 8 * ROWW;
                ah[mt][0] = Ash[r0];     ah[mt][1] = Ash[r1];
                ah[mt][2] = Ash[r0 + 4]; ah[mt][3] = Ash[r1 + 4];
                al[mt][0] = Asl[r0];     al[mt][1] = Asl[r1];
                al[mt][2] = Asl[r0 + 4]; al[mt][3] = Asl[r1 + 4];
            }
#pragma unroll
            for (int nt = 0; nt < 4; nt++) {
                int n0 = (wc * 32 + nt * 8 + g) * ROWW + kw + t;
                bh[nt][0] = Bsh[n0]; bh[nt][1] = Bsh[n0 + 4];
                bl[nt][0] = Bsl[n0]; bl[nt][1] = Bsl[n0 + 4];
            }
#pragma unroll
            for (int mt = 0; mt < 4; mt++)
#pragma unroll
                for (int nt = 0; nt < 4; nt++) {
                    mma16816(acc[mt][nt], ah[mt], bh[nt]);
                    mma16816(acc[mt][nt], ah[mt], bl[nt]);
                    mma16816(acc[mt][nt], al[mt], bh[nt]);
                }
        }

        // ---- epilogue for this chunk ----
#pragma unroll
        for (int mt = 0; mt < 4; mt++) {
            int row0 = m0 + wr * 64 + mt * 16 + g;
            int row1 = row0 + 8;
#pragma unroll
            for (int nt = 0; nt < 4; nt++) {
                int col = wc * 32 + nt * 8 + 2 * t;
                int ocol = ch * 128 + col;
                float b0 = __ldg(bias + ocol), b1 = __ldg(bias + ocol + 1);
                if (row0 < M) {
                    float2 o;
                    o.x = acc[mt][nt][0] + b0;
                    o.y = acc[mt][nt][1] + b1;
                    if (MODE == 1) {
                        float2 xr = *(const float2*)(Xres + (size_t)row0 * CDIM + col);
                        o.x = beta * o.x + omb * xr.x;
                        o.y = beta * o.y + omb * xr.y;
                    }
                    *(float2*)(Cout + (size_t)row0 * ldc + ocol) = o;
                }
                if (row1 < M) {
                    float2 o;
                    o.x = acc[mt][nt][2] + b0;
                    o.y = acc[mt][nt][3] + b1;
                    if (MODE == 1) {
                        float2 xr = *(const float2*)(Xres + (size_t)row1 * CDIM + col);
                        o.x = beta * o.x + omb * xr.x;
                        o.y = beta * o.y + omb * xr.y;
                    }
                    *(float2*)(Cout + (size_t)row1 * ldc + ocol) = o;
                }
            }
        }
        __syncthreads();
    }
}

// ---------------- fused edge pass: 2 edges per warp, strided projections ------
__global__ __launch_bounds__(256) void edge_fused_k(
    const int* __restrict__ eidx, int E,
    const float* __restrict__ q, int ldq,
    const float* __restrict__ kr, int ldk,
    const float* __restrict__ vr, int ldv,
    const float* __restrict__ prel,
    float* __restrict__ ssum, float* __restrict__ aggR) {
    int w = (blockIdx.x * blockDim.x + threadIdx.x) >> 5;
    int e0 = w * 2;
    if (e0 >= E) return;
    int e1 = e0 + 1;
    bool has1 = (e1 < E);
    int lane = threadIdx.x & 31;
    int h = lane >> 2;
    float pr = __ldg(prel + h);

    int src0 = __ldg(eidx + e0);
    int dst0 = __ldg(eidx + E + e0);
    int src1 = has1 ? __ldg(eidx + e1) : src0;
    int dst1 = has1 ? __ldg(eidx + E + e1) : dst0;

    float4 q0 = *(const float4*)(q + (size_t)dst0 * ldq + lane * 4);
    float4 k0 = *(const float4*)(kr + (size_t)src0 * ldk + lane * 4);
    float4 v0 = *(const float4*)(vr + (size_t)src0 * ldv + lane * 4);
    float4 q1 = *(const float4*)(q + (size_t)dst1 * ldq + lane * 4);
    float4 k1 = *(const float4*)(kr + (size_t)src1 * ldk + lane * 4);
    float4 v1 = *(const float4*)(vr + (size_t)src1 * ldv + lane * 4);

    float p0 = q0.x * k0.x + q0.y * k0.y + q0.z * k0.z + q0.w * k0.w;
    float p1 = q1.x * k1.x + q1.y * k1.y + q1.z * k1.z + q1.w * k1.w;
    p0 += __shfl_xor_sync(0xffffffffu, p0, 1);
    p1 += __shfl_xor_sync(0xffffffffu, p1, 1);
    p0 += __shfl_xor_sync(0xffffffffu, p0, 2);
    p1 += __shfl_xor_sync(0xffffffffu, p1, 2);

    float ev0 = __expf(p0 * 0.25f * pr);
    float ev1 = __expf(p1 * 0.25f * pr);

    if ((lane & 3) == 0) {
        atomicAdd(ssum + (size_t)dst0 * HDIM + h, ev0);
        if (has1) atomicAdd(ssum + (size_t)dst1 * HDIM + h, ev1);
    }
    float* ap0 = aggR + (size_t)dst0 * CDIM + lane * 4;
    asm volatile("red.global.add.v4.f32 [%0], {%1, %2, %3, %4};"
                 :: "l"(ap0), "f"(v0.x * ev0), "f"(v0.y * ev0), "f"(v0.z * ev0), "f"(v0.w * ev0)
                 : "memory");
    if (has1) {
        float* ap1 = aggR + (size_t)dst1 * CDIM + lane * 4;
        asm volatile("red.global.add.v4.f32 [%0], {%1, %2, %3, %4};"
                     :: "l"(ap1), "f"(v1.x * ev1), "f"(v1.y * ev1), "f"(v1.z * ev1), "f"(v1.w * ev1)
                     : "memory");
    }
}

// ---------------- launch ----------------
extern "C" void kernel_launch(void* const* d_in, const int* in_sizes, int n_in,
                              void* d_out, int out_size) {
    const float* xA = (const float*)d_in[0];
    const float* xB = (const float*)d_in[1];
    const int* eAB = (const int*)d_in[2];
    const int* eBA = (const int*)d_in[3];
    const int* eAA = (const int*)d_in[4];
    const float* Wk = (const float*)d_in[5];
    const float* bk = (const float*)d_in[6];
    const float* Wq = (const float*)d_in[7];
    const float* bq = (const float*)d_in[8];
    const float* Wv = (const float*)d_in[9];
    const float* bv = (const float*)d_in[10];
    const float* Wa = (const float*)d_in[11];
    const float* ba = (const float*)d_in[12];
    const float* skip = (const float*)d_in[13];
    const float* a_rel = (const float*)d_in[14];
    const float* m_rel = (const float*)d_in[15];
    const float* p_rel = (const float*)d_in[16];
    float* out = (float*)d_out;

    int NA = in_sizes[0] / CDIM;
    int NB = in_sizes[1] / CDIM;
    int E0 = in_sizes[2] / 2;
    int E1 = in_sizes[3] / 2;
    int E2 = in_sizes[4] / 2;

    float *projA, *projB, *ssum, *aggR, *biasA, *biasB;
    __nv_bfloat16 *WTh, *WTl, *xAh, *xAl, *xBh, *xBl;
    cudaGetSymbolAddress((void**)&projA, g_projA);
    cudaGetSymbolAddress((void**)&projB, g_projB);
    cudaGetSymbolAddress((void**)&ssum, g_sum);
    cudaGetSymbolAddress((void**)&aggR, g_aggR);
    cudaGetSymbolAddress((void**)&biasA, g_biasA);
    cudaGetSymbolAddress((void**)&biasB, g_biasB);
    cudaGetSymbolAddress((void**)&WTh, g_WTh);
    cudaGetSymbolAddress((void**)&WTl, g_WTl);
    cudaGetSymbolAddress((void**)&xAh, g_xAh);
    cudaGetSymbolAddress((void**)&xAl, g_xAl);
    cudaGetSymbolAddress((void**)&xBh, g_xBh);
    cudaGetSymbolAddress((void**)&xBl, g_xBl);

    cudaFuncSetAttribute(hgemm_multi_k<5, 0>, cudaFuncAttributeMaxDynamicSharedMemorySize, GSM_TOTAL);
    cudaFuncSetAttribute(hgemm_multi_k<3, 0>, cudaFuncAttributeMaxDynamicSharedMemorySize, GSM_TOTAL);
    cudaFuncSetAttribute(hgemm_multi_k<1, 1>, cudaFuncAttributeMaxDynamicSharedMemorySize, GSM_TOTAL);

    cudaMemsetAsync(ssum, 0, (size_t)3 * NMAX * HDIM * sizeof(float));
    cudaMemsetAsync(aggR, 0, (size_t)3 * NMAX * CDIM * sizeof(float));

    prep_weights_k<<<dim3(CDIM, 3), CDIM>>>(Wk, bk, Wv, bv, a_rel, m_rel);
    biascat_k<<<(LDA + LDB + 255) / 256, 256>>>(bq);
    wcvt_k<<<10, 256>>>(Wq, Wa);
    cvt_k<<<(NA * 32 + 255) / 256, 256>>>(xA, xAh, xAl, NA * 32);
    cvt_k<<<(NB * 32 + 255) / 256, 256>>>(xB, xBh, xBl, NB * 32);

    const int CC = CDIM * CDIM;
    const size_t NC = (size_t)NMAX * CDIM;
    const size_t NH = (size_t)NMAX * HDIM;
    dim3 gA((NA + 127) / 128), gB((NB + 127) / 128);

    // 2 wide projection GEMMs (A staged once, B chunks looped)
    hgemm_multi_k<5, 0><<<gA, 256, GSM_TOTAL>>>(xAh, xAl, WTh + 0 * CC, WTl + 0 * CC,
                                                biasA, nullptr, 0, nullptr, projA, LDA, NA);
    hgemm_multi_k<3, 0><<<gB, 256, GSM_TOTAL>>>(xBh, xBl, WTh + 5 * CC, WTl + 5 * CC,
                                                biasB, nullptr, 0, nullptr, projB, LDB, NB);

    // fused edge passes (2 edges/warp). projA: q=0 kr0=128 kr2=256 vr0=384 vr2=512; projB: q=0 kr1=128 vr1=256
    auto eblocks = [](int E) { return ((E + 1) / 2 + 7) / 8; };
    edge_fused_k<<<eblocks(E0), 256>>>(eAB, E0, projB, LDB, projA + 128, LDA, projA + 384, LDA,
                                       p_rel + 0, ssum + 0 * NH, aggR + 0 * NC);
    edge_fused_k<<<eblocks(E1), 256>>>(eBA, E1, projA, LDA, projB + 128, LDB, projB + 256, LDB,
                                       p_rel + 8, ssum + 1 * NH, aggR + 1 * NC);
    edge_fused_k<<<eblocks(E2), 256>>>(eAA, E2, projA, LDA, projA + 256, LDA, projA + 512, LDA,
                                       p_rel + 16, ssum + 2 * NH, aggR + 2 * NC);

    // epilogue: normalize+gelu pre-pass into bf16 hi/lo (reuse x buffers), then GEMM+blend
    geluprep_k<<<(NA * 32 + 255) / 256, 256>>>(aggR + 1 * NC, aggR + 2 * NC, ssum + 1 * NH, ssum + 2 * NH, xAh, xAl, NA);
    geluprep_k<<<(NB * 32 + 255) / 256, 256>>>(aggR + 0 * NC, nullptr, ssum + 0 * NH, nullptr, xBh, xBl, NB);
    hgemm_multi_k<1, 1><<<gA, 256, GSM_TOTAL>>>(xAh, xAl, WTh + 8 * CC, WTl + 8 * CC,
                                                ba, skip, 0, xA, out, CDIM, NA);
    hgemm_multi_k<1, 1><<<gB, 256, GSM_TOTAL>>>(xBh, xBl, WTh + 9 * CC, WTl + 9 * CC,
                                                ba + CDIM, skip, 1, xB, out + (size_t)NA * CDIM, CDIM, NB);
}